// round 6
// baseline (speedup 1.0000x reference)
#include <cuda_runtime.h>

// Problem constants (B, S, K) = (512, 2048, 17)
#define BB 512
#define SS 2048
#define KK 17
#define SK (SS * KK)
#define TILE 32            // scan steps per emission tile
#define TILEF (TILE * KK)  // 544 floats = 2176 B per tile
#define SEQ_PER_BLK 4

__device__ float g_part[BB];   // per-sequence (logZ - numerator)

__device__ __forceinline__ void cp16(void* smem, const void* gmem) {
    unsigned s = (unsigned)__cvta_generic_to_shared(smem);
    asm volatile("cp.async.cg.shared.global [%0], [%1], 16;\n" :: "r"(s), "l"(gmem));
}
#define CP_COMMIT() asm volatile("cp.async.commit_group;\n" ::: "memory")
#define CP_WAIT1()  asm volatile("cp.async.wait_group 1;\n" ::: "memory")

// copy one 544-float tile (136 x 16B) global -> shared via cp.async
__device__ __forceinline__ void load_tile(float* dst, const float* src, int lane) {
    #pragma unroll
    for (int r = 0; r < 4; r++)
        cp16(dst + (lane + 32 * r) * 4, src + (lane + 32 * r) * 4);
    if (lane < 8)
        cp16(dst + (128 + lane) * 4, src + (128 + lane) * 4);
}

__global__ __launch_bounds__(512) void crf_kernel(
    const float* __restrict__ em,      // [B,S,K]
    const float* __restrict__ startT,  // [K]
    const float* __restrict__ endT,    // [K]
    const float* __restrict__ trans,   // [K,K]
    const int*   __restrict__ labels,  // [B,S]
    const int*   __restrict__ attn,    // [B,S]
    float* __restrict__ out,           // [0]=loss, [1..]=emissions copy
    int copy_emissions)
{
    const int tid  = threadIdx.x;
    const int wid  = tid >> 5;
    const int lane = tid & 31;

    // --- warps 4..15: stream-copy this block's 4 sequences of emissions ---
    if (wid >= 4) {
        if (copy_emissions) {
            const size_t base = (size_t)blockIdx.x * SEQ_PER_BLK * SK;
            const float4* s4 = (const float4*)(em + base);
            float* dst = out + 1 + base;             // 4B-aligned only -> scalar stores
            const int n4 = SEQ_PER_BLK * SK / 4;     // 34816 float4s
            #pragma unroll 2
            for (int i = tid - 128; i < n4; i += 384) {
                float4 v = s4[i];
                dst[4 * i + 0] = v.x;
                dst[4 * i + 1] = v.y;
                dst[4 * i + 2] = v.z;
                dst[4 * i + 3] = v.w;
            }
        }
        return;
    }

    // --- warps 0..3: each scans one sequence (one warp per SMSP) ---
    const int b = blockIdx.x * SEQ_PER_BLK + wid;
    const float* emb = em + (size_t)b * SK;
    const int*   lab = labels + (size_t)b * SS;
    const int*   msk = attn   + (size_t)b * SS;

    __shared__ __align__(16) float ebuf[SEQ_PER_BLK][2][TILEF];
    __shared__ __align__(16) float arow[SEQ_PER_BLK][32];   // alpha broadcast row
    __shared__ unsigned mask_bits[SEQ_PER_BLK][SS / 32];

    // exp(transitions) column for this lane's state j (tiny, L1/L2 resident)
    float w[KK];
    #pragma unroll
    for (int i = 0; i < KK; i++)
        w[i] = (lane < KK) ? __expf(__ldg(&trans[i * KK + lane])) : 0.0f;

    // ---- numerator pass + mask bit packing + seq-end stats ----
    float numv = 0.0f;
    int cnt = 0, lastidx = 0;
    for (int t = lane; t < SS; t += 32) {
        int lt = lab[t];
        int m  = (msk[t] != 0) && (lt >= 0);
        unsigned bal = __ballot_sync(0xffffffffu, m);
        if (lane == 0) mask_bits[wid][t >> 5] = bal;
        if (m) {
            cnt++;
            lastidx = t;
            if (t > 0) {
                int ltc = (lt == -100) ? 0 : lt;
                int lp  = lab[t - 1];
                int lpc = (lp == -100) ? 0 : lp;
                numv += __ldg(&trans[lpc * KK + ltc]) + emb[t * KK + ltc];
            }
        }
    }
    #pragma unroll
    for (int o = 16; o; o >>= 1) {
        numv += __shfl_xor_sync(0xffffffffu, numv, o);
        cnt  += __shfl_xor_sync(0xffffffffu, cnt,  o);
        lastidx = max(lastidx, __shfl_xor_sync(0xffffffffu, lastidx, o));
    }
    {
        int l0  = lab[0];
        int l0c = (l0 == -100) ? 0 : l0;
        int se  = max(cnt - 1, 0);
        int le  = lab[se];
        int lec = (le == -100) ? 0 : le;
        numv += startT[l0c] + emb[l0c] + endT[lec];
    }
    __syncwarp();   // mask_bits visible within this warp

    // ---- alpha_0 in linear space, carried log-scale M ----
    float al = (lane < KK) ? (startT[lane] + emb[lane]) : -1e30f;
    float M = al;
    #pragma unroll
    for (int o = 16; o; o >>= 1)
        M = fmaxf(M, __shfl_xor_sync(0xffffffffu, M, o));
    float a = (lane < KK) ? __expf(al - M) : 0.0f;

    const int lasttile = lastidx / TILE;

    // prologue: async-load tiles 0 and 1 (2 committed groups invariant)
    load_tile(ebuf[wid][0], emb, lane);
    CP_COMMIT();
    if (lasttile >= 1)
        load_tile(ebuf[wid][1], emb + TILEF, lane);
    CP_COMMIT();

    // shared addresses for the warp-synchronous alpha broadcast
    const unsigned ar_base = (unsigned)__cvta_generic_to_shared(&arow[wid][0]);
    const unsigned st_addr = ar_base + 4u * lane;

    // ---- forward scan over uniform 32-step tiles ----
    for (int tb = 0; tb <= lasttile; tb++) {
        CP_WAIT1();            // tile tb complete (<=1 group pending)
        __syncwarp();          // cross-lane visibility of cp.async data

        const float* eb = ebuf[wid][tb & 1];
        unsigned mword = mask_bits[wid][tb];
        if (tb == 0) mword &= ~1u;      // step t=0 does not exist

        #pragma unroll 8
        for (int tt = 0; tt < TILE; ++tt) {
            float e = eb[tt * KK + lane];   // lanes>=17 read other data; harmless
            float g = __expf(e);

            // warp-synchronous broadcast of alpha through shared memory.
            // Convergent warp: STS then LDS issue in order through the
            // in-order per-warp LSU path; volatile asms pin compiler order.
            asm volatile("st.shared.f32 [%0], %1;" :: "r"(st_addr), "f"(a));
            float v0x, v0y, v0z, v0w, v1x, v1y, v1z, v1w;
            float v2x, v2y, v2z, v2w, v3x, v3y, v3z, v3w, v16;
            asm volatile("ld.shared.v4.f32 {%0,%1,%2,%3}, [%4];"
                         : "=f"(v0x), "=f"(v0y), "=f"(v0z), "=f"(v0w) : "r"(ar_base));
            asm volatile("ld.shared.v4.f32 {%0,%1,%2,%3}, [%4];"
                         : "=f"(v1x), "=f"(v1y), "=f"(v1z), "=f"(v1w) : "r"(ar_base + 16));
            asm volatile("ld.shared.v4.f32 {%0,%1,%2,%3}, [%4];"
                         : "=f"(v2x), "=f"(v2y), "=f"(v2z), "=f"(v2w) : "r"(ar_base + 32));
            asm volatile("ld.shared.v4.f32 {%0,%1,%2,%3}, [%4];"
                         : "=f"(v3x), "=f"(v3y), "=f"(v3z), "=f"(v3w) : "r"(ar_base + 48));
            asm volatile("ld.shared.f32 %0, [%1];"
                         : "=f"(v16) : "r"(ar_base + 64));

            float s0 = v0x * w[0];
            float s1 = v0y * w[1];
            float s2 = v0z * w[2];
            float s3 = v0w * w[3];
            s0 = fmaf(v1x, w[4],  s0);
            s1 = fmaf(v1y, w[5],  s1);
            s2 = fmaf(v1z, w[6],  s2);
            s3 = fmaf(v1w, w[7],  s3);
            s0 = fmaf(v2x, w[8],  s0);
            s1 = fmaf(v2y, w[9],  s1);
            s2 = fmaf(v2z, w[10], s2);
            s3 = fmaf(v2w, w[11], s3);
            s0 = fmaf(v3x, w[12], s0);
            s1 = fmaf(v3y, w[13], s1);
            s2 = fmaf(v3z, w[14], s2);
            s3 = fmaf(v3w, w[15], s3);
            s0 = fmaf(v16, w[16], s0);
            float s = (s0 + s1) + (s2 + s3);

            bool m = (mword >> tt) & 1u;
            float anew = s * g;
            a = m ? anew : a;

            if ((tt & 7) == 0) {
                // renorm by exact power of two from max(previous alpha)
                float m0 = fmaxf(fmaxf(v0x, v0y), fmaxf(v0z, v0w));
                float m1 = fmaxf(fmaxf(v1x, v1y), fmaxf(v1z, v1w));
                float m2 = fmaxf(fmaxf(v2x, v2y), fmaxf(v2z, v2w));
                float m3 = fmaxf(fmaxf(v3x, v3y), fmaxf(v3z, v3w));
                float mx = fmaxf(fmaxf(m0, m1), fmaxf(fmaxf(m2, m3), v16));
                int e2 = (__float_as_int(mx) >> 23) - 127;       // floor(log2 mx)
                float scale = __int_as_float((127 - e2) << 23);  // exact 2^-e2
                a *= scale;
                M += (float)e2 * 0.6931471805599453f;
            }
        }

        // start async load of tile tb+2, keep 2-group invariant
        if (tb + 2 <= lasttile)
            load_tile(ebuf[wid][tb & 1], emb + (size_t)(tb + 2) * TILEF, lane);
        CP_COMMIT();
    }

    // ---- log_z = M + log( sum_j a_j * exp(end_j) ) ----
    float zterm = (lane < KK) ? a * __expf(endT[lane]) : 0.0f;
    #pragma unroll
    for (int o = 16; o; o >>= 1)
        zterm += __shfl_xor_sync(0xffffffffu, zterm, o);
    float logz = M + __logf(zterm);

    if (lane == 0)
        g_part[b] = logz - numv;
}

__global__ void reduce_kernel(float* __restrict__ out)
{
    __shared__ float sh[128];
    int t = threadIdx.x;
    float v = 0.0f;
    #pragma unroll
    for (int i = 0; i < BB / 128; i++)
        v += g_part[t + 128 * i];
    sh[t] = v;
    __syncthreads();
    #pragma unroll
    for (int s2 = 64; s2; s2 >>= 1) {
        if (t < s2) sh[t] += sh[t + s2];
        __syncthreads();
    }
    if (t == 0) out[0] = sh[0] * (1.0f / (float)BB);
}

extern "C" void kernel_launch(void* const* d_in, const int* in_sizes, int n_in,
                              void* d_out, int out_size)
{
    const float* em  = (const float*)d_in[0];
    const float* st  = (const float*)d_in[1];
    const float* en  = (const float*)d_in[2];
    const float* tr  = (const float*)d_in[3];
    const int*   lab = (const int*)d_in[4];
    const int*   att = (const int*)d_in[5];
    float* out = (float*)d_out;

    int copy = (out_size > in_sizes[0]) ? 1 : 0;

    crf_kernel<<<BB / SEQ_PER_BLK, 512>>>(em, st, en, tr, lab, att, out, copy);
    reduce_kernel<<<1, 128>>>(out);
}

// round 7
// speedup vs baseline: 2.6601x; 2.6601x over previous
#include <cuda_runtime.h>

// Problem constants (B, S, K) = (512, 2048, 17)
#define BB 512
#define SS 2048
#define KK 17
#define SK (SS * KK)
#define CHUNKS 16
#define CL 128              // steps owned per chunk: t in [c*CL, (c+1)*CL-1]
#define TSTEPS 16           // steps per emission tile
#define TILEF (TSTEPS * KK) // 272 floats = 1088 B, 16B-aligned per tile
#define SCAN_WPB 8          // scan warps per block
#define NCOPY_BLOCKS 512
#define NSCAN_BLOCKS ((BB * CHUNKS) / SCAN_WPB)   // 1024

__device__ float g_part2[BB * CHUNKS];   // per-(seq,chunk) loss contribution

__device__ __forceinline__ void cp16(void* smem, const void* gmem) {
    unsigned s = (unsigned)__cvta_generic_to_shared(smem);
    asm volatile("cp.async.cg.shared.global [%0], [%1], 16;\n" :: "r"(s), "l"(gmem));
}
#define CP_COMMIT() asm volatile("cp.async.commit_group;\n" ::: "memory")
#define CP_WAIT1()  asm volatile("cp.async.wait_group 1;\n" ::: "memory")

// one 272-float tile (68 x 16B) global -> shared via cp.async
__device__ __forceinline__ void load_tile(float* dst, const float* src, int lane) {
    cp16(dst + lane * 4,        src + lane * 4);
    cp16(dst + (32 + lane) * 4, src + (32 + lane) * 4);
    if (lane < 4)
        cp16(dst + (64 + lane) * 4, src + (64 + lane) * 4);
}

__global__ __launch_bounds__(256) void crf_kernel(
    const float* __restrict__ em,      // [B,S,K]
    const float* __restrict__ startT,  // [K]
    const float* __restrict__ endT,    // [K]
    const float* __restrict__ trans,   // [K,K]
    const int*   __restrict__ labels,  // [B,S]
    const int*   __restrict__ attn,    // [B,S]
    float* __restrict__ out,           // [0]=loss, [1..]=emissions copy
    int copy_emissions)
{
    // ---- copy blocks first (overlap with scan waves) ----
    if (blockIdx.x < NCOPY_BLOCKS) {
        if (!copy_emissions) return;
        const size_t base = (size_t)blockIdx.x * SK;
        const float4* s4 = (const float4*)(em + base);
        float* dst = out + 1 + base;          // 4B-aligned -> scalar stores
        #pragma unroll 2
        for (int i = threadIdx.x; i < SK / 4; i += 256) {
            float4 v = s4[i];
            dst[4 * i + 0] = v.x;
            dst[4 * i + 1] = v.y;
            dst[4 * i + 2] = v.z;
            dst[4 * i + 3] = v.w;
        }
        return;
    }

    // ---- scan blocks: 8 warps, each = one (sequence, chunk) ----
    const int tid  = threadIdx.x;
    const int wid  = tid >> 5;
    const int lane = tid & 31;
    const int gw   = (blockIdx.x - NCOPY_BLOCKS) * SCAN_WPB + wid;
    const int b    = gw / CHUNKS;
    const int c    = gw % CHUNKS;

    const float* emb = em + (size_t)b * SK;
    const int*   lab = labels + (size_t)b * SS;
    const int*   msk = attn   + (size_t)b * SS;

    __shared__ __align__(16) float ebuf[SCAN_WPB][2][TILEF];
    __shared__ __align__(16) float arow[SCAN_WPB][32];

    // ---- phase 1: masks + numerator for steps t in [c*CL, (c+1)*CL) ----
    const int tbase = c * CL;
    unsigned mwords[4];
    float numv = 0.0f;
    #pragma unroll
    for (int r = 0; r < 4; r++) {
        int t  = tbase + 32 * r + lane;
        int lt = lab[t];
        bool m = (msk[t] != 0) && (lt >= 0);
        mwords[r] = __ballot_sync(0xffffffffu, m);
        if (m && t > 0) {
            int lp  = lab[t - 1];
            int lpc = (lp < 0) ? 0 : lp;
            numv += __ldg(&trans[lpc * KK + lt]) + emb[t * KK + lt];
        }
    }
    #pragma unroll
    for (int o = 16; o; o >>= 1)
        numv += __shfl_xor_sync(0xffffffffu, numv, o);

    // active: chunk has any owned step in-mask (mask is a prefix)
    bool active = (c == 0) || ((mwords[0] & 1u) != 0);
    if (!active) {
        if (lane == 0) g_part2[gw] = 0.0f;
        return;
    }

    // contains the global last masked index?
    bool mnext = false;
    if (c < CHUNKS - 1) {
        int t = (c + 1) * CL;
        mnext = (msk[t] != 0) && (lab[t] >= 0);
    }
    const bool contains = !mnext;

    if (contains) {   // numerator end term (uniform across lanes)
        int li = 0;
        if      (mwords[3]) li = tbase + 96 + (31 - __clz(mwords[3]));
        else if (mwords[2]) li = tbase + 64 + (31 - __clz(mwords[2]));
        else if (mwords[1]) li = tbase + 32 + (31 - __clz(mwords[1]));
        else if (mwords[0]) li = tbase +      (31 - __clz(mwords[0]));
        int ll = lab[li];
        numv += endT[(ll < 0) ? 0 : ll];
    }
    if (c == 0) {
        int l0  = lab[0];
        int l0c = (l0 < 0) ? 0 : l0;
        numv += startT[l0c] + emb[l0c];
    }

    // exp(transitions) column for this lane's state
    float w[KK];
    #pragma unroll
    for (int i = 0; i < KK; i++)
        w[i] = (lane < KK) ? __expf(__ldg(&trans[i * KK + lane])) : 0.0f;

    // ---- alpha init ----
    float a, M;
    if (c == 0) {
        float al = (lane < KK) ? (startT[lane] + emb[lane]) : -1e30f;
        M = al;
        #pragma unroll
        for (int o = 16; o; o >>= 1)
            M = fmaxf(M, __shfl_xor_sync(0xffffffffu, M, o));
        a = (lane < KK) ? __expf(al - M) : 0.0f;
    } else {
        a = (lane < KK) ? 1.0f : 0.0f;     // uniform warm-up start
        M = 0.0f;
    }
    float base = 0.0f;                      // chunk 0: absolute reference

    // tile schedule: c==0 -> tiles 0..7 (steps 0..127, step 0 masked off)
    //                c>=1 -> tiles 8c-1 .. 8c+7 (16 warm-up + 128 owned steps)
    const int k0     = (c == 0) ? 0 : 8 * c - 1;
    const int ntiles = (c == 0) ? 8 : 9;

    load_tile(ebuf[wid][0], emb + (size_t)k0 * TILEF, lane);
    CP_COMMIT();
    load_tile(ebuf[wid][1], emb + (size_t)(k0 + 1) * TILEF, lane);
    CP_COMMIT();

    for (int j = 0; j < ntiles; j++) {
        CP_WAIT1();
        __syncwarp();

        const float* eb = ebuf[wid][j & 1];
        const bool wutile = (c > 0) && (j == 0);
        unsigned mw;
        if (wutile) {
            mw = 0xFFFFu;                            // warm-up: fully in-mask
        } else {
            int jm = (c > 0) ? j - 1 : j;            // owned-tile index 0..7
            mw = (mwords[jm >> 1] >> (16 * (jm & 1))) & 0xFFFFu;
            if (c == 0 && jm == 0) mw &= ~1u;        // t=0 is not a step
        }

        #pragma unroll 8
        for (int tt = 0; tt < TSTEPS; ++tt) {
            float e = eb[tt * KK + lane];   // lanes>=17 read junk; harmless
            float g = __expf(e);

            // broadcast previous alpha through shared memory
            arow[wid][lane] = a;
            __syncwarp();
            const float* ar = arow[wid];
            float4 v0 = *(const float4*)&ar[0];
            float4 v1 = *(const float4*)&ar[4];
            float4 v2 = *(const float4*)&ar[8];
            float4 v3 = *(const float4*)&ar[12];
            float  v16 = ar[16];

            float s0 = v0.x * w[0];
            float s1 = v0.y * w[1];
            float s2 = v0.z * w[2];
            float s3 = v0.w * w[3];
            s0 = fmaf(v1.x, w[4],  s0);
            s1 = fmaf(v1.y, w[5],  s1);
            s2 = fmaf(v1.z, w[6],  s2);
            s3 = fmaf(v1.w, w[7],  s3);
            s0 = fmaf(v2.x, w[8],  s0);
            s1 = fmaf(v2.y, w[9],  s1);
            s2 = fmaf(v2.z, w[10], s2);
            s3 = fmaf(v2.w, w[11], s3);
            s0 = fmaf(v3.x, w[12], s0);
            s1 = fmaf(v3.y, w[13], s1);
            s2 = fmaf(v3.z, w[14], s2);
            s3 = fmaf(v3.w, w[15], s3);
            s0 = fmaf(v16,  w[16], s0);
            float s = (s0 + s1) + (s2 + s3);

            bool m = (mw >> tt) & 1u;
            float anew = s * g;
            a = m ? anew : a;

            if ((tt & 7) == 0) {
                // renorm by exact power of two from max(previous alpha)
                float m0 = fmaxf(fmaxf(v0.x, v0.y), fmaxf(v0.z, v0.w));
                float m1 = fmaxf(fmaxf(v1.x, v1.y), fmaxf(v1.z, v1.w));
                float m2 = fmaxf(fmaxf(v2.x, v2.y), fmaxf(v2.z, v2.w));
                float m3 = fmaxf(fmaxf(v3.x, v3.y), fmaxf(v3.z, v3.w));
                float mx = fmaxf(fmaxf(m0, m1), fmaxf(fmaxf(m2, m3), v16));
                int e2 = (__float_as_int(mx) >> 23) - 127;
                float scale = __int_as_float((127 - e2) << 23);
                a *= scale;
                M += (float)e2 * 0.6931471805599453f;
            }
            __syncwarp();   // arow reusable next step
        }

        if (wutile) {
            // snapshot: base = log n(alpha at chunk start), n = sum
            float zs = a;
            #pragma unroll
            for (int o = 16; o; o >>= 1)
                zs += __shfl_xor_sync(0xffffffffu, zs, o);
            base = M + __logf(zs);
        }

        if (j + 2 < ntiles)
            load_tile(ebuf[wid][j & 1], emb + (size_t)(k0 + j + 2) * TILEF, lane);
        CP_COMMIT();
    }

    // ---- chunk contribution ----
    float zterm = (lane < KK) ? (contains ? a * __expf(endT[lane]) : a) : 0.0f;
    #pragma unroll
    for (int o = 16; o; o >>= 1)
        zterm += __shfl_xor_sync(0xffffffffu, zterm, o);
    float fin = M + __logf(zterm);

    if (lane == 0)
        g_part2[gw] = (fin - base) - numv;
}

__global__ void reduce_kernel(float* __restrict__ out)
{
    __shared__ float sh[256];
    int t = threadIdx.x;
    float v = 0.0f;
    #pragma unroll
    for (int i = 0; i < (BB * CHUNKS) / 256; i++)
        v += g_part2[t + 256 * i];
    sh[t] = v;
    __syncthreads();
    #pragma unroll
    for (int s2 = 128; s2; s2 >>= 1) {
        if (t < s2) sh[t] += sh[t + s2];
        __syncthreads();
    }
    if (t == 0) out[0] = sh[0] * (1.0f / (float)BB);
}

extern "C" void kernel_launch(void* const* d_in, const int* in_sizes, int n_in,
                              void* d_out, int out_size)
{
    const float* em  = (const float*)d_in[0];
    const float* st  = (const float*)d_in[1];
    const float* en  = (const float*)d_in[2];
    const float* tr  = (const float*)d_in[3];
    const int*   lab = (const int*)d_in[4];
    const int*   att = (const int*)d_in[5];
    float* out = (float*)d_out;

    int copy = (out_size > in_sizes[0]) ? 1 : 0;

    crf_kernel<<<NCOPY_BLOCKS + NSCAN_BLOCKS, 256>>>(em, st, en, tr, lab, att, out, copy);
    reduce_kernel<<<1, 256>>>(out);
}